// round 5
// baseline (speedup 1.0000x reference)
#include <cuda_runtime.h>

// ---------------- problem constants ----------------
#define TBS   128          // T*B = 4*32
#define SEQ   81           // 9*9
#define CH    128          // width C
#define MROWS (TBS*SEQ)    // 10368 rows
#define NQKV  384          // 3*C
#define EPSLN 1e-5f

typedef unsigned long long ull;

// ---------------- scratch (static device globals; no allocation) ------------
__device__ float  g_h  [MROWS*CH];    // residual stream
__device__ float2 g_stats[MROWS];     // per-row (mu, rstd) of g_h
__device__ float  g_qkv[MROWS*NQKV];  // qkv projection
__device__ float  g_att[MROWS*CH];    // attention output

// ---------------- packed f32x2 helpers --------------------------------------
__device__ __forceinline__ ull pk2(float x, float y) {
    ull r;
    asm("mov.b64 %0, {%1, %2};"
        : "=l"(r) : "r"(__float_as_uint(x)), "r"(__float_as_uint(y)));
    return r;
}
__device__ __forceinline__ ull fma2(ull a, ull b, ull c) {
    ull d;
    asm("fma.rn.f32x2 %0, %1, %2, %3;" : "=l"(d) : "l"(a), "l"(b), "l"(c));
    return d;
}
__device__ __forceinline__ void upk2(ull v, float& x, float& y) {
    unsigned int lo, hi;
    asm("mov.b64 {%0, %1}, %2;" : "=r"(lo), "=r"(hi) : "l"(v));
    x = __uint_as_float(lo);
    y = __uint_as_float(hi);
}
__device__ __forceinline__ float ex2(float x) {
    float r;
    asm("ex2.approx.f32 %0, %1;" : "=f"(r) : "f"(x));
    return r;
}

// ---------------- input projection + LN stats --------------------------------
__global__ void __launch_bounds__(256) inproj_kernel(const float* __restrict__ x,
                                                     const float* __restrict__ in_w,
                                                     const float* __restrict__ in_b) {
    int row  = blockIdx.x * 8 + (threadIdx.x >> 5);
    int lane = threadIdx.x & 31;
    float x0 = __ldg(&x[row * 2]);
    float x1 = __ldg(&x[row * 2 + 1]);
    float s = 0.f, ss = 0.f;
    float* hr = g_h + (size_t)row * CH;
#pragma unroll
    for (int j = 0; j < 4; j++) {
        int c = lane + 32 * j;
        float h = fmaf(x0, in_w[c], fmaf(x1, in_w[CH + c], in_b[c]));
        hr[c] = h;
        s += h;
        ss = fmaf(h, h, ss);
    }
#pragma unroll
    for (int o = 16; o; o >>= 1) {
        s  += __shfl_xor_sync(0xffffffffu, s, o);
        ss += __shfl_xor_sync(0xffffffffu, ss, o);
    }
    if (lane == 0) {
        float mu  = s * (1.0f / CH);
        float var = fmaf(-mu, mu, ss * (1.0f / CH));
        g_stats[row] = make_float2(mu, rsqrtf(var + EPSLN));
    }
}

// ---------------- fused LN + QKV GEMM ----------------------------------------
// A[m][k] = (g_h[m][k]-mu)*rstd*gam[k]+bet[k]; g_qkv = A@W + bias.
// tile 64M x 128N, 256 threads, 4 rows x 8 cols/thread, N-pair f32x2 packing.
__global__ void __launch_bounds__(256) qkv_gemm(const float* __restrict__ W,
                                                const float* __restrict__ bias,
                                                const float* __restrict__ gam,
                                                const float* __restrict__ bet) {
    __shared__ float gsh[CH], bsh[CH];
    __shared__ __align__(16) float As[16][64];
    __shared__ __align__(16) float Bs[16][128];

    int tid = threadIdx.x;
    if (tid < 128) gsh[tid] = gam[tid];
    else           bsh[tid - 128] = bet[tid - 128];

    int tx = tid & 15;              // col group: 8*tx .. +7
    int ty = tid >> 4;              // row group: 4*ty .. +3

    int arow = tid & 63;            // A staging row
    int akh  = (tid >> 6) << 2;     // A staging k offset: 0,4,8,12
    int bk   = tid >> 4;            // B staging k row: 0..15
    int bc   = (tid & 15) << 3;     // B staging col: 0..120

    size_t gRow = (size_t)blockIdx.y * 64 + arow;
    const float* hp = g_h + gRow * CH;
    float2 st = g_stats[gRow];
    float c1 = st.y;                // rstd
    float c0 = -st.x * st.y;        // -mu*rstd
    const float* Bp = W + (size_t)bk * NQKV + blockIdx.x * 128 + bc;

    ull acc[4][4];
#pragma unroll
    for (int m = 0; m < 4; m++)
#pragma unroll
        for (int j = 0; j < 4; j++) acc[m][j] = 0ull;

    __syncthreads();                // gsh/bsh ready

    for (int k0 = 0; k0 < CH; k0 += 16) {
        float4 hv = *(const float4*)(hp + k0 + akh);
        float4 b0 = *(const float4*)(Bp + (size_t)k0 * NQKV);
        float4 b1 = *(const float4*)(Bp + (size_t)k0 * NQKV + 4);
        float av[4] = {hv.x, hv.y, hv.z, hv.w};
#pragma unroll
        for (int j = 0; j < 4; j++) {
            int kk = akh + j;
            As[kk][arow] = fmaf(fmaf(av[j], c1, c0), gsh[k0 + kk], bsh[k0 + kk]);
        }
        *(float4*)&Bs[bk][bc]     = b0;
        *(float4*)&Bs[bk][bc + 4] = b1;
        __syncthreads();
#pragma unroll
        for (int k = 0; k < 16; k++) {
            ulonglong2 q0 = *(const ulonglong2*)&Bs[k][8 * tx];      // cols 8tx..+3
            ulonglong2 q1 = *(const ulonglong2*)&Bs[k][8 * tx + 4];  // cols +4..+7
            ull bp2[4] = {q0.x, q0.y, q1.x, q1.y};
#pragma unroll
            for (int m = 0; m < 4; m++) {
                float a = As[k][4 * ty + m];                         // broadcast
                ull aa = pk2(a, a);
#pragma unroll
                for (int j = 0; j < 4; j++)
                    acc[m][j] = fma2(aa, bp2[j], acc[m][j]);
            }
        }
        __syncthreads();
    }

    int colBase = blockIdx.x * 128 + 8 * tx;
    float bb[8];
    *(float4*)(bb)     = *(const float4*)(bias + colBase);
    *(float4*)(bb + 4) = *(const float4*)(bias + colBase + 4);
#pragma unroll
    for (int m = 0; m < 4; m++) {
        size_t row = (size_t)blockIdx.y * 64 + 4 * ty + m;
        float v[8];
#pragma unroll
        for (int j = 0; j < 4; j++) upk2(acc[m][j], v[2 * j], v[2 * j + 1]);
#pragma unroll
        for (int j = 0; j < 8; j++) v[j] += bb[j];
        float* o = g_qkv + row * NQKV + colBase;
        *(float4*)(o)     = make_float4(v[0], v[1], v[2], v[3]);
        *(float4*)(o + 4) = make_float4(v[4], v[5], v[6], v[7]);
    }
}

// ---------------- fused per-channel attention (unchanged, proven) ------------
#define QT 9
#define KT 27
__global__ void __launch_bounds__(128, 8) attn_kernel() {
    int b  = blockIdx.y;
    int q0 = blockIdx.x * QT;
    int c  = threadIdx.x;

    __shared__ float ks[KT][CH];
    __shared__ float vs[KT][CH];

    const float* base = g_qkv + (size_t)b * SEQ * NQKV;
    const float LOG2E = 1.4426950408889634f;

    float qv[QT], num[QT], den[QT];
#pragma unroll
    for (int i = 0; i < QT; i++) {
        qv[i]  = base[(size_t)(q0 + i) * NQKV + c] * LOG2E;
        num[i] = 0.f;
        den[i] = 0.f;
    }

#pragma unroll 1
    for (int kc = 0; kc < SEQ; kc += KT) {
        __syncthreads();
#pragma unroll
        for (int r = 0; r < KT; r++) {
            ks[r][c] = base[(size_t)(kc + r) * NQKV + CH     + c];
            vs[r][c] = base[(size_t)(kc + r) * NQKV + 2 * CH + c];
        }
        __syncthreads();
#pragma unroll 3
        for (int r = 0; r < KT; r++) {
            float kk = ks[r][c];
            float vv = vs[r][c];
#pragma unroll
            for (int i = 0; i < QT; i++) {
                float e = ex2(qv[i] * kk);
                num[i] = fmaf(e, vv, num[i]);
                den[i] += e;
            }
        }
    }

    float* op = g_att + ((size_t)b * SEQ + q0) * CH + c;
#pragma unroll
    for (int i = 0; i < QT; i++) op[(size_t)i * CH] = __fdividef(num[i], den[i]);
}

// ---------------- full GEMM + relu + residual + LN stats ---------------------
// g_h += relu(g_att @ W + bias); emits (mu, rstd) per updated row.
// tile 32M x 128N, 256 threads, 2 rows x 8 cols/thread, N-pair f32x2 packing.
__global__ void __launch_bounds__(256) full_gemm(const float* __restrict__ W,
                                                 const float* __restrict__ bias) {
    __shared__ __align__(16) float As[16][32];
    __shared__ __align__(16) float Bs[16][128];

    int tid = threadIdx.x;
    int tx = tid & 15;              // cols 8*tx .. +7
    int ty = tid >> 4;              // rows 2*ty .. +1

    int arow = tid & 31;            // A staging row
    int akh  = (tid >> 5) << 1;     // A staging k offset: 0,2,..,14
    int bk   = tid >> 4;
    int bc   = (tid & 15) << 3;

    size_t rowsBase = (size_t)blockIdx.x * 32;
    const float* ap = g_att + (rowsBase + arow) * CH + akh;
    const float* Bp = W + (size_t)bk * CH + bc;

    ull acc[2][4];
#pragma unroll
    for (int m = 0; m < 2; m++)
#pragma unroll
        for (int j = 0; j < 4; j++) acc[m][j] = 0ull;

    for (int k0 = 0; k0 < CH; k0 += 16) {
        float2 a2 = *(const float2*)(ap + k0);
        float4 b0 = *(const float4*)(Bp + (size_t)k0 * CH);
        float4 b1 = *(const float4*)(Bp + (size_t)k0 * CH + 4);
        As[akh][arow]     = a2.x;
        As[akh + 1][arow] = a2.y;
        *(float4*)&Bs[bk][bc]     = b0;
        *(float4*)&Bs[bk][bc + 4] = b1;
        __syncthreads();
#pragma unroll
        for (int k = 0; k < 16; k++) {
            ulonglong2 q0 = *(const ulonglong2*)&Bs[k][8 * tx];
            ulonglong2 q1 = *(const ulonglong2*)&Bs[k][8 * tx + 4];
            ull bp2[4] = {q0.x, q0.y, q1.x, q1.y};
#pragma unroll
            for (int m = 0; m < 2; m++) {
                float a = As[k][2 * ty + m];
                ull aa = pk2(a, a);
#pragma unroll
                for (int j = 0; j < 4; j++)
                    acc[m][j] = fma2(aa, bp2[j], acc[m][j]);
            }
        }
        __syncthreads();
    }

    int colBase = 8 * tx;
    float bb[8];
    *(float4*)(bb)     = *(const float4*)(bias + colBase);
    *(float4*)(bb + 4) = *(const float4*)(bias + colBase + 4);
    float s[2], ss[2];
#pragma unroll
    for (int m = 0; m < 2; m++) {
        size_t row = rowsBase + 2 * ty + m;
        float v[8];
#pragma unroll
        for (int j = 0; j < 4; j++) upk2(acc[m][j], v[2 * j], v[2 * j + 1]);
        float* hrow = g_h + row * CH + colBase;
        float4 o0 = *(const float4*)(hrow);
        float4 o1 = *(const float4*)(hrow + 4);
        float hn[8];
        hn[0] = o0.x + fmaxf(v[0] + bb[0], 0.f);
        hn[1] = o0.y + fmaxf(v[1] + bb[1], 0.f);
        hn[2] = o0.z + fmaxf(v[2] + bb[2], 0.f);
        hn[3] = o0.w + fmaxf(v[3] + bb[3], 0.f);
        hn[4] = o1.x + fmaxf(v[4] + bb[4], 0.f);
        hn[5] = o1.y + fmaxf(v[5] + bb[5], 0.f);
        hn[6] = o1.z + fmaxf(v[6] + bb[6], 0.f);
        hn[7] = o1.w + fmaxf(v[7] + bb[7], 0.f);
        *(float4*)(hrow)     = make_float4(hn[0], hn[1], hn[2], hn[3]);
        *(float4*)(hrow + 4) = make_float4(hn[4], hn[5], hn[6], hn[7]);
        float t = 0.f, tt = 0.f;
#pragma unroll
        for (int j = 0; j < 8; j++) {
            t += hn[j];
            tt = fmaf(hn[j], hn[j], tt);
        }
        s[m] = t;
        ss[m] = tt;
    }
    // reduce across the 16 lanes (tx) that share each row (half-warp groups)
#pragma unroll
    for (int m = 0; m < 2; m++) {
#pragma unroll
        for (int o = 8; o; o >>= 1) {
            s[m]  += __shfl_xor_sync(0xffffffffu, s[m], o);
            ss[m] += __shfl_xor_sync(0xffffffffu, ss[m], o);
        }
    }
    if (tx == 0) {
#pragma unroll
        for (int m = 0; m < 2; m++) {
            size_t row = rowsBase + 2 * ty + m;
            float mu  = s[m] * (1.0f / CH);
            float var = fmaf(-mu, mu, ss[m] * (1.0f / CH));
            g_stats[row] = make_float2(mu, rsqrtf(var + EPSLN));
        }
    }
}

// ---------------- final projection: out = h @ out_w + out_b ------------------
__global__ void __launch_bounds__(256) outproj_kernel(const float* __restrict__ ow,
                                                      const float* __restrict__ ob,
                                                      float* __restrict__ out) {
    int row  = blockIdx.x * 8 + (threadIdx.x >> 5);
    int lane = threadIdx.x & 31;
    const float* hr = g_h + (size_t)row * CH;
    float a0 = 0.f, a1 = 0.f, a2 = 0.f, a3 = 0.f;
#pragma unroll
    for (int j = 0; j < 4; j++) {
        int cidx = lane + 32 * j;
        float hv = hr[cidx];
        const float* w = ow + cidx * 4;
        a0 = fmaf(hv, w[0], a0);
        a1 = fmaf(hv, w[1], a1);
        a2 = fmaf(hv, w[2], a2);
        a3 = fmaf(hv, w[3], a3);
    }
#pragma unroll
    for (int o = 16; o; o >>= 1) {
        a0 += __shfl_xor_sync(0xffffffffu, a0, o);
        a1 += __shfl_xor_sync(0xffffffffu, a1, o);
        a2 += __shfl_xor_sync(0xffffffffu, a2, o);
        a3 += __shfl_xor_sync(0xffffffffu, a3, o);
    }
    if (lane == 0) {
        *(float4*)(out + (size_t)row * 4) =
            make_float4(a0 + ob[0], a1 + ob[1], a2 + ob[2], a3 + ob[3]);
    }
}

// ---------------- launch -----------------------------------------------------
extern "C" void kernel_launch(void* const* d_in, const int* in_sizes, int n_in,
                              void* d_out, int out_size) {
    const float* x      = (const float*)d_in[0];
    const float* in_w   = (const float*)d_in[1];
    const float* in_b   = (const float*)d_in[2];
    const float* ln_g   = (const float*)d_in[3];
    const float* ln_b   = (const float*)d_in[4];
    const float* qkv_w  = (const float*)d_in[5];
    const float* qkv_b  = (const float*)d_in[6];
    const float* full_w = (const float*)d_in[7];
    const float* full_b = (const float*)d_in[8];
    const float* out_w  = (const float*)d_in[9];
    const float* out_b  = (const float*)d_in[10];
    float* out = (float*)d_out;

    inproj_kernel<<<MROWS / 8, 256>>>(x, in_w, in_b);

    for (int l = 0; l < 4; l++) {
        qkv_gemm<<<dim3(NQKV / 128, MROWS / 64), 256>>>(
            qkv_w + (size_t)l * CH * NQKV, qkv_b + l * NQKV,
            ln_g + l * CH, ln_b + l * CH);
        attn_kernel<<<dim3(SEQ / QT, TBS), 128>>>();
        full_gemm<<<MROWS / 32, 256>>>(
            full_w + (size_t)l * CH * CH, full_b + l * CH);
    }

    outproj_kernel<<<MROWS / 8, 256>>>(out_w, out_b, out);
}

// round 7
// speedup vs baseline: 1.3682x; 1.3682x over previous
#include <cuda_runtime.h>

// ---------------- problem constants ----------------
#define TBS   128          // T*B = 4*32
#define SEQ   81           // 9*9
#define CH    128          // width C
#define MROWS (TBS*SEQ)    // 10368 rows
#define NQKV  384          // 3*C
#define EPSLN 1e-5f

typedef unsigned long long ull;

// ---------------- scratch (static device globals; no allocation) ------------
__device__ float  g_h  [MROWS*CH];    // residual stream
__device__ float2 g_stats[MROWS];     // per-row (mu, rstd) of g_h
__device__ float  g_qkv[MROWS*NQKV];  // qkv projection
__device__ float  g_att[MROWS*CH];    // attention output

// ---------------- packed f32x2 helpers --------------------------------------
__device__ __forceinline__ ull pk2(float x, float y) {
    ull r;
    asm("mov.b64 %0, {%1, %2};"
        : "=l"(r) : "r"(__float_as_uint(x)), "r"(__float_as_uint(y)));
    return r;
}
__device__ __forceinline__ ull fma2(ull a, ull b, ull c) {
    ull d;
    asm("fma.rn.f32x2 %0, %1, %2, %3;" : "=l"(d) : "l"(a), "l"(b), "l"(c));
    return d;
}
__device__ __forceinline__ void upk2(ull v, float& x, float& y) {
    unsigned int lo, hi;
    asm("mov.b64 {%0, %1}, %2;" : "=r"(lo), "=r"(hi) : "l"(v));
    x = __uint_as_float(lo);
    y = __uint_as_float(hi);
}
__device__ __forceinline__ float ex2(float x) {
    float r;
    asm("ex2.approx.f32 %0, %1;" : "=f"(r) : "f"(x));
    return r;
}

// ---------------- input projection + LN stats --------------------------------
__global__ void __launch_bounds__(256) inproj_kernel(const float* __restrict__ x,
                                                     const float* __restrict__ in_w,
                                                     const float* __restrict__ in_b) {
    int row  = blockIdx.x * 8 + (threadIdx.x >> 5);
    int lane = threadIdx.x & 31;
    float x0 = __ldg(&x[row * 2]);
    float x1 = __ldg(&x[row * 2 + 1]);
    float s = 0.f, ss = 0.f;
    float* hr = g_h + (size_t)row * CH;
#pragma unroll
    for (int j = 0; j < 4; j++) {
        int c = lane + 32 * j;
        float h = fmaf(x0, in_w[c], fmaf(x1, in_w[CH + c], in_b[c]));
        hr[c] = h;
        s += h;
        ss = fmaf(h, h, ss);
    }
#pragma unroll
    for (int o = 16; o; o >>= 1) {
        s  += __shfl_xor_sync(0xffffffffu, s, o);
        ss += __shfl_xor_sync(0xffffffffu, ss, o);
    }
    if (lane == 0) {
        float mu  = s * (1.0f / CH);
        float var = fmaf(-mu, mu, ss * (1.0f / CH));
        g_stats[row] = make_float2(mu, rsqrtf(var + EPSLN));
    }
}

// ---------------- fused LN + QKV GEMM ----------------------------------------
// 128M x 128N tile, 256 threads, 8x8 per thread, double-buffered smem.
// A[m][k] = (g_h[m][k]-mu)*rstd*gam[k]+bet[k]; g_qkv = A@W + bias.
__global__ void __launch_bounds__(256) qkv_gemm(const float* __restrict__ W,
                                                const float* __restrict__ bias,
                                                const float* __restrict__ gam,
                                                const float* __restrict__ bet) {
    __shared__ float gsh[CH], bsh[CH];
    __shared__ __align__(16) float As[2][16][128];
    __shared__ __align__(16) float Bs[2][16][128];

    int tid = threadIdx.x;
    if (tid < 128) { gsh[tid] = gam[tid]; bsh[tid] = bet[tid]; }

    int tx = tid & 15;              // output cols 8*tx .. +7
    int ty = tid >> 4;              // output rows 8*ty .. +7

    int arow = tid & 127;           // A staging: row
    int akh  = (tid >> 7) << 3;     // A staging: k half (0 or 8)
    int brow = tid >> 4;            // B staging: k row 0..15
    int bcol = (tid & 15) << 3;     // B staging: col

    size_t mBase = (size_t)blockIdx.y * 128;
    int    nBase = blockIdx.x * 128;
    const float* hp = g_h + (mBase + arow) * CH + akh;
    float2 st = g_stats[mBase + arow];
    float c1 = st.y;                // rstd
    float c0 = -st.x * st.y;        // -mu*rstd
    const float* Bp = W + (size_t)brow * NQKV + nBase + bcol;

    ull acc[8][4];
#pragma unroll
    for (int m = 0; m < 8; m++)
#pragma unroll
        for (int j = 0; j < 4; j++) acc[m][j] = 0ull;

    // prologue: fetch chunk 0
    float4 pa0 = *(const float4*)(hp);
    float4 pa1 = *(const float4*)(hp + 4);
    float4 pb0 = *(const float4*)(Bp);
    float4 pb1 = *(const float4*)(Bp + 4);
    __syncthreads();                // gsh/bsh visible
    {
        float av[8] = {pa0.x, pa0.y, pa0.z, pa0.w, pa1.x, pa1.y, pa1.z, pa1.w};
#pragma unroll
        for (int j = 0; j < 8; j++) {
            int kk = akh + j;
            As[0][kk][arow] = fmaf(fmaf(av[j], c1, c0), gsh[kk], bsh[kk]);
        }
        *(float4*)&Bs[0][brow][bcol]     = pb0;
        *(float4*)&Bs[0][brow][bcol + 4] = pb1;
    }
    __syncthreads();

#pragma unroll
    for (int i = 0; i < 8; i++) {
        int buf = i & 1;
        if (i < 7) {                // prefetch next chunk into regs
            const float* hq = hp + (i + 1) * 16;
            const float* bq = Bp + (size_t)(i + 1) * 16 * NQKV;
            pa0 = *(const float4*)(hq);
            pa1 = *(const float4*)(hq + 4);
            pb0 = *(const float4*)(bq);
            pb1 = *(const float4*)(bq + 4);
        }
#pragma unroll
        for (int k = 0; k < 16; k++) {
            float4 aA = *(const float4*)&As[buf][k][8 * ty];
            float4 aB = *(const float4*)&As[buf][k][8 * ty + 4];
            ulonglong2 q0 = *(const ulonglong2*)&Bs[buf][k][8 * tx];
            ulonglong2 q1 = *(const ulonglong2*)&Bs[buf][k][8 * tx + 4];
            ull bp2[4] = {q0.x, q0.y, q1.x, q1.y};
            float am[8] = {aA.x, aA.y, aA.z, aA.w, aB.x, aB.y, aB.z, aB.w};
#pragma unroll
            for (int m = 0; m < 8; m++) {
                ull aa = pk2(am[m], am[m]);
#pragma unroll
                for (int j = 0; j < 4; j++)
                    acc[m][j] = fma2(aa, bp2[j], acc[m][j]);
            }
        }
        if (i < 7) {                // stage next chunk into other buffer
            int nb = buf ^ 1;
            int k0 = (i + 1) * 16;
            float av[8] = {pa0.x, pa0.y, pa0.z, pa0.w, pa1.x, pa1.y, pa1.z, pa1.w};
#pragma unroll
            for (int j = 0; j < 8; j++) {
                int kk = akh + j;
                As[nb][kk][arow] = fmaf(fmaf(av[j], c1, c0), gsh[k0 + kk], bsh[k0 + kk]);
            }
            *(float4*)&Bs[nb][brow][bcol]     = pb0;
            *(float4*)&Bs[nb][brow][bcol + 4] = pb1;
            __syncthreads();
        }
    }

    int colBase = nBase + 8 * tx;
    float bb[8];
    *(float4*)(bb)     = *(const float4*)(bias + colBase);
    *(float4*)(bb + 4) = *(const float4*)(bias + colBase + 4);
#pragma unroll
    for (int m = 0; m < 8; m++) {
        size_t row = mBase + 8 * ty + m;
        float v[8];
#pragma unroll
        for (int j = 0; j < 4; j++) upk2(acc[m][j], v[2 * j], v[2 * j + 1]);
#pragma unroll
        for (int j = 0; j < 8; j++) v[j] += bb[j];
        float* o = g_qkv + row * NQKV + colBase;
        *(float4*)(o)     = make_float4(v[0], v[1], v[2], v[3]);
        *(float4*)(o + 4) = make_float4(v[4], v[5], v[6], v[7]);
    }
}

// ---------------- fused per-channel attention (unchanged, proven) ------------
#define QT 9
#define KT 27
__global__ void __launch_bounds__(128, 8) attn_kernel() {
    int b  = blockIdx.y;
    int q0 = blockIdx.x * QT;
    int c  = threadIdx.x;

    __shared__ float ks[KT][CH];
    __shared__ float vs[KT][CH];

    const float* base = g_qkv + (size_t)b * SEQ * NQKV;
    const float LOG2E = 1.4426950408889634f;

    float qv[QT], num[QT], den[QT];
#pragma unroll
    for (int i = 0; i < QT; i++) {
        qv[i]  = base[(size_t)(q0 + i) * NQKV + c] * LOG2E;
        num[i] = 0.f;
        den[i] = 0.f;
    }

#pragma unroll 1
    for (int kc = 0; kc < SEQ; kc += KT) {
        __syncthreads();
#pragma unroll
        for (int r = 0; r < KT; r++) {
            ks[r][c] = base[(size_t)(kc + r) * NQKV + CH     + c];
            vs[r][c] = base[(size_t)(kc + r) * NQKV + 2 * CH + c];
        }
        __syncthreads();
#pragma unroll 3
        for (int r = 0; r < KT; r++) {
            float kk = ks[r][c];
            float vv = vs[r][c];
#pragma unroll
            for (int i = 0; i < QT; i++) {
                float e = ex2(qv[i] * kk);
                num[i] = fmaf(e, vv, num[i]);
                den[i] += e;
            }
        }
    }

    float* op = g_att + ((size_t)b * SEQ + q0) * CH + c;
#pragma unroll
    for (int i = 0; i < QT; i++) op[(size_t)i * CH] = __fdividef(num[i], den[i]);
}

// ---------------- full GEMM + relu + residual + LN stats ---------------------
// 64M x 128N tile, 128 threads, 8x8 per thread, double-buffered smem.
// g_h += relu(g_att @ W + bias); emits (mu, rstd) per updated row.
__global__ void __launch_bounds__(128) full_gemm(const float* __restrict__ W,
                                                 const float* __restrict__ bias) {
    __shared__ __align__(16) float As[2][16][64];
    __shared__ __align__(16) float Bs[2][16][128];

    int tid = threadIdx.x;
    int tx = tid & 15;              // cols 8*tx .. +7
    int ty = tid >> 4;              // rows 8*ty .. +7 (ty 0..7)

    int arow = tid & 63;            // A staging: row
    int akh  = (tid >> 6) << 3;     // A staging: k half (0 or 8)
    int brow = tid >> 3;            // B staging: k row 0..15
    int bcol = (tid & 7) << 4;      // B staging: col (16 wide)

    size_t mBase = (size_t)blockIdx.x * 64;
    const float* ap = g_att + (mBase + arow) * CH + akh;
    const float* Bp = W + (size_t)brow * CH + bcol;

    ull acc[8][4];
#pragma unroll
    for (int m = 0; m < 8; m++)
#pragma unroll
        for (int j = 0; j < 4; j++) acc[m][j] = 0ull;

    // prologue: chunk 0
    float4 pa0 = *(const float4*)(ap);
    float4 pa1 = *(const float4*)(ap + 4);
    float4 pb0 = *(const float4*)(Bp);
    float4 pb1 = *(const float4*)(Bp + 4);
    float4 pb2 = *(const float4*)(Bp + 8);
    float4 pb3 = *(const float4*)(Bp + 12);
    {
        float av[8] = {pa0.x, pa0.y, pa0.z, pa0.w, pa1.x, pa1.y, pa1.z, pa1.w};
#pragma unroll
        for (int j = 0; j < 8; j++) As[0][akh + j][arow] = av[j];
        *(float4*)&Bs[0][brow][bcol]      = pb0;
        *(float4*)&Bs[0][brow][bcol + 4]  = pb1;
        *(float4*)&Bs[0][brow][bcol + 8]  = pb2;
        *(float4*)&Bs[0][brow][bcol + 12] = pb3;
    }
    __syncthreads();

#pragma unroll
    for (int i = 0; i < 8; i++) {
        int buf = i & 1;
        if (i < 7) {
            const float* aq = ap + (i + 1) * 16;
            const float* bq = Bp + (size_t)(i + 1) * 16 * CH;
            pa0 = *(const float4*)(aq);
            pa1 = *(const float4*)(aq + 4);
            pb0 = *(const float4*)(bq);
            pb1 = *(const float4*)(bq + 4);
            pb2 = *(const float4*)(bq + 8);
            pb3 = *(const float4*)(bq + 12);
        }
#pragma unroll
        for (int k = 0; k < 16; k++) {
            float4 aA = *(const float4*)&As[buf][k][8 * ty];
            float4 aB = *(const float4*)&As[buf][k][8 * ty + 4];
            ulonglong2 q0 = *(const ulonglong2*)&Bs[buf][k][8 * tx];
            ulonglong2 q1 = *(const ulonglong2*)&Bs[buf][k][8 * tx + 4];
            ull bp2[4] = {q0.x, q0.y, q1.x, q1.y};
            float am[8] = {aA.x, aA.y, aA.z, aA.w, aB.x, aB.y, aB.z, aB.w};
#pragma unroll
            for (int m = 0; m < 8; m++) {
                ull aa = pk2(am[m], am[m]);
#pragma unroll
                for (int j = 0; j < 4; j++)
                    acc[m][j] = fma2(aa, bp2[j], acc[m][j]);
            }
        }
        if (i < 7) {
            int nb = buf ^ 1;
            float av[8] = {pa0.x, pa0.y, pa0.z, pa0.w, pa1.x, pa1.y, pa1.z, pa1.w};
#pragma unroll
            for (int j = 0; j < 8; j++) As[nb][akh + j][arow] = av[j];
            *(float4*)&Bs[nb][brow][bcol]      = pb0;
            *(float4*)&Bs[nb][brow][bcol + 4]  = pb1;
            *(float4*)&Bs[nb][brow][bcol + 8]  = pb2;
            *(float4*)&Bs[nb][brow][bcol + 12] = pb3;
            __syncthreads();
        }
    }

    int colBase = 8 * tx;
    float bb[8];
    *(float4*)(bb)     = *(const float4*)(bias + colBase);
    *(float4*)(bb + 4) = *(const float4*)(bias + colBase + 4);
    float s[8], ss[8];
#pragma unroll
    for (int m = 0; m < 8; m++) {
        size_t row = mBase + 8 * ty + m;
        float v[8];
#pragma unroll
        for (int j = 0; j < 4; j++) upk2(acc[m][j], v[2 * j], v[2 * j + 1]);
        float* hrow = g_h + row * CH + colBase;
        float4 o0 = *(const float4*)(hrow);
        float4 o1 = *(const float4*)(hrow + 4);
        float hn[8];
        hn[0] = o0.x + fmaxf(v[0] + bb[0], 0.f);
        hn[1] = o0.y + fmaxf(v[1] + bb[1], 0.f);
        hn[2] = o0.z + fmaxf(v[2] + bb[2], 0.f);
        hn[3] = o0.w + fmaxf(v[3] + bb[3], 0.f);
        hn[4] = o1.x + fmaxf(v[4] + bb[4], 0.f);
        hn[5] = o1.y + fmaxf(v[5] + bb[5], 0.f);
        hn[6] = o1.z + fmaxf(v[6] + bb[6], 0.f);
        hn[7] = o1.w + fmaxf(v[7] + bb[7], 0.f);
        *(float4*)(hrow)     = make_float4(hn[0], hn[1], hn[2], hn[3]);
        *(float4*)(hrow + 4) = make_float4(hn[4], hn[5], hn[6], hn[7]);
        float t = 0.f, tt = 0.f;
#pragma unroll
        for (int j = 0; j < 8; j++) {
            t += hn[j];
            tt = fmaf(hn[j], hn[j], tt);
        }
        s[m] = t;
        ss[m] = tt;
    }
    // reduce over the 16 tx lanes sharing each row (stay inside 16-lane group)
#pragma unroll
    for (int m = 0; m < 8; m++) {
#pragma unroll
        for (int o = 8; o; o >>= 1) {
            s[m]  += __shfl_xor_sync(0xffffffffu, s[m], o);
            ss[m] += __shfl_xor_sync(0xffffffffu, ss[m], o);
        }
    }
    if (tx == 0) {
#pragma unroll
        for (int m = 0; m < 8; m++) {
            size_t row = mBase + 8 * ty + m;
            float mu  = s[m] * (1.0f / CH);
            float var = fmaf(-mu, mu, ss[m] * (1.0f / CH));
            g_stats[row] = make_float2(mu, rsqrtf(var + EPSLN));
        }
    }
}

// ---------------- final projection: out = h @ out_w + out_b ------------------
__global__ void __launch_bounds__(256) outproj_kernel(const float* __restrict__ ow,
                                                      const float* __restrict__ ob,
                                                      float* __restrict__ out) {
    int row  = blockIdx.x * 8 + (threadIdx.x >> 5);
    int lane = threadIdx.x & 31;
    const float* hr = g_h + (size_t)row * CH;
    float a0 = 0.f, a1 = 0.f, a2 = 0.f, a3 = 0.f;
#pragma unroll
    for (int j = 0; j < 4; j++) {
        int cidx = lane + 32 * j;
        float hv = hr[cidx];
        const float* w = ow + cidx * 4;
        a0 = fmaf(hv, w[0], a0);
        a1 = fmaf(hv, w[1], a1);
        a2 = fmaf(hv, w[2], a2);
        a3 = fmaf(hv, w[3], a3);
    }
#pragma unroll
    for (int o = 16; o; o >>= 1) {
        a0 += __shfl_xor_sync(0xffffffffu, a0, o);
        a1 += __shfl_xor_sync(0xffffffffu, a1, o);
        a2 += __shfl_xor_sync(0xffffffffu, a2, o);
        a3 += __shfl_xor_sync(0xffffffffu, a3, o);
    }
    if (lane == 0) {
        *(float4*)(out + (size_t)row * 4) =
            make_float4(a0 + ob[0], a1 + ob[1], a2 + ob[2], a3 + ob[3]);
    }
}

// ---------------- launch -----------------------------------------------------
extern "C" void kernel_launch(void* const* d_in, const int* in_sizes, int n_in,
                              void* d_out, int out_size) {
    const float* x      = (const float*)d_in[0];
    const float* in_w   = (const float*)d_in[1];
    const float* in_b   = (const float*)d_in[2];
    const float* ln_g   = (const float*)d_in[3];
    const float* ln_b   = (const float*)d_in[4];
    const float* qkv_w  = (const float*)d_in[5];
    const float* qkv_b  = (const float*)d_in[6];
    const float* full_w = (const float*)d_in[7];
    const float* full_b = (const float*)d_in[8];
    const float* out_w  = (const float*)d_in[9];
    const float* out_b  = (const float*)d_in[10];
    float* out = (float*)d_out;

    inproj_kernel<<<MROWS / 8, 256>>>(x, in_w, in_b);

    for (int l = 0; l < 4; l++) {
        qkv_gemm<<<dim3(NQKV / 128, MROWS / 128), 256>>>(
            qkv_w + (size_t)l * CH * NQKV, qkv_b + l * NQKV,
            ln_g + l * CH, ln_b + l * CH);
        attn_kernel<<<dim3(SEQ / QT, TBS), 128>>>();
        full_gemm<<<MROWS / 64, 128>>>(
            full_w + (size_t)l * CH * CH, full_b + l * CH);
    }

    outproj_kernel<<<MROWS / 8, 256>>>(out_w, out_b, out);
}